// round 5
// baseline (speedup 1.0000x reference)
#include <cuda_runtime.h>
#include <cstdint>

// Radon: out[b,n,t] = sum_h bilinear(img_b, R(theta_n)*grid(t,h)).  B=2, N=180, H=W=512.
//
// Band decomposition: image split into 5 horizontal bands (104 rows x 517 cols, ~210KB smem).
// One block per (band, angle-group, batch) = 140 blocks of 1024 threads = 1 wave, each
// loads its band ONCE and accumulates the partial sums of samples whose y lies in the band.
// Exact fp ownership partition (same bitwise y in every block) -> no atomics, deterministic.

#define IMG 512
#define NANG 180
#define NB 2

#define NBANDS 5
#define NGROUPS 14
#define ANG_PER_G 13          // 13*13 + 11 = 180

#define BROWS 104             // stored rows per band (incl. shared/halo row)
#define SPITCH 517            // 515 content cols (x=-1..513) + 2 pad; 517%32=5, gcd=1
#define SMEM_BYTES (BROWS * SPITCH * 4)

__device__ float d_part[NBANDS * NB * NANG * IMG];

__global__ void __launch_bounds__(1024, 1)
radon_band_kernel(const float* __restrict__ xin, const float* __restrict__ angles) {
    extern __shared__ float sm[];

    const int group = blockIdx.x;          // 0..13
    const int band  = blockIdx.y;          // 0..4
    const int b     = blockIdx.z;          // batch

    // Band tables (ownership edges at y = 102,205,308,411; storage rows rowbase..rowbase+103)
    const int   rowbase_t[NBANDS] = { -1, 102, 205, 308, 411 };
    const float yloO_t[NBANDS] = { -1e30f, 102.f, 205.f, 308.f, 411.f };  // ownership lo
    const float yhiO_t[NBANDS] = { 102.f, 205.f, 308.f, 411.f, 1e30f };   // ownership hi
    const float yloC_t[NBANDS] = { -1.f, 102.f, 205.f, 308.f, 411.f };    // clamp lo
    const float yhiC_t[NBANDS] = { 102.f, 205.f, 308.f, 411.f, 512.f };   // clamp hi
    const float yloI_t[NBANDS] = { -2.f, 102.f, 205.f, 308.f, 411.f };    // interval lo
    const float yhiI_t[NBANDS] = { 102.f, 205.f, 308.f, 411.f, 514.f };   // interval hi

    const int   rowbase = rowbase_t[band];
    const float yloO = yloO_t[band], yhiO = yhiO_t[band];
    const float yloC = yloC_t[band], yhiC = yhiC_t[band];
    const float yloI = yloI_t[band], yhiI = yhiI_t[band];

    const int tid = threadIdx.x;

    // ---- Fill band tile: rows rowbase..rowbase+103, cols x=-1..513 at col index x+1 ----
    const float* __restrict__ img = xin + b * (IMG * IMG);
    for (int idx = tid; idx < BROWS * SPITCH; idx += 1024) {
        int r  = idx / SPITCH;
        int cc = idx - r * SPITCH;
        int yg = rowbase + r;
        int xg = cc - 1;
        float v = 0.0f;
        if ((unsigned)yg < IMG && (unsigned)xg < IMG) v = img[yg * IMG + xg];
        sm[idx] = v;
    }
    __syncthreads();

    const int warp = tid >> 5;
    const int lane = tid & 31;
    const int i = lane & 7;            // t within 8-wide tile
    const int p = lane >> 3;           // h phase 0..3

    const int n0 = group * ANG_PER_G;
    const int nang = min(ANG_PER_G, NANG - n0);
    const int nunits = nang * (IMG / 8);

    float* __restrict__ part = d_part + ((band * NB + b) * NANG) * IMG;

    for (int u = warp; u < nunits; u += 32) {
        const int a  = u >> 6;         // angle within group
        const int tt = u & 63;         // t-tile
        const int n  = n0 + a;
        const int t0 = tt * 8;

        const float ang = angles[n] * 0.017453292519943295f;
        const float s = sinf(ang);
        const float c = cosf(ang);
        const float ns = -s;
        const float I0 = 255.5f * (s - c + 1.0f);
        const float J0 = 255.5f * (1.0f - s - c);

        const float t_f = (float)(t0 + i);
        const float tix0 = fmaf(t_f, c, I0);
        const float tiy0 = fmaf(t_f, s, J0);

        // warp-uniform conservative h-interval from tile-corner t values
        const float tyA = fmaf((float)t0, s, J0), tyB = fmaf((float)(t0 + 7), s, J0);
        const float txA = fmaf((float)t0, c, I0), txB = fmaf((float)(t0 + 7), c, I0);
        const float tymin = fminf(tyA, tyB), tymax = fmaxf(tyA, tyB);
        const float txmin = fminf(txA, txB), txmax = fmaxf(txA, txB);

        float hy0, hy1, hx0, hx1;
        if (fabsf(c) > 1e-5f) {
            const float inv = 1.0f / c;
            const float hA = (yloI - tymax) * inv;
            const float hB = (yhiI - tymin) * inv;
            hy0 = fminf(hA, hB); hy1 = fmaxf(hA, hB);
        } else { hy0 = 0.0f; hy1 = 512.0f; }
        if (fabsf(s) > 1e-5f) {
            const float inv = 1.0f / s;
            const float hA = (txmin - 514.0f) * inv;  // x(h) = tx - h*s in [-2, 514]
            const float hB = (txmax + 2.0f) * inv;
            hx0 = fminf(hA, hB); hx1 = fmaxf(hA, hB);
        } else { hx0 = 0.0f; hx1 = 512.0f; }

        const float hs_f = fmaxf(fmaxf(hy0, hx0) - 1.0f, 0.0f);
        const float he_f = fminf(fminf(hy1, hx1) + 1.0f, 512.0f);
        const int hs = __float2int_rd(hs_f);
        const int he = __float2int_ru(he_f);

        float acc = 0.0f;
        if (he > hs) {
            const int kmax = (he - hs - p + 3) >> 2;   // h = hs + p + 4k < he
            float hf = (float)(hs + p);
#pragma unroll 2
            for (int k = 0; k < kmax; ++k) {
                const float yg = fmaf(hf, c, tiy0);    // bitwise-identical across bands
                const float xg = fmaf(hf, ns, tix0);
                const bool valid = (yg >= yloO) && (yg < yhiO);

                const float yc = fminf(fmaxf(yg, yloC), yhiC);
                const float xc = fminf(fmaxf(xg, -1.0f), 512.0f);
                const int xi = __float2int_rd(xc);
                const int yi = __float2int_rd(yc);
                const float fx = xc - (float)xi;
                const float fy = yc - (float)yi;

                int rel = yi - rowbase;
                rel = min(rel, BROWS - 2);             // address safety for invalid lanes

                const float* pp = sm + rel * SPITCH + (xi + 1);
                const float v00 = pp[0];
                const float v10 = pp[1];
                const float v01 = pp[SPITCH];
                const float v11 = pp[SPITCH + 1];
                const float top = fmaf(fx, v10 - v00, v00);
                const float bot = fmaf(fx, v11 - v01, v01);
                const float contrib = fmaf(fy, bot - top, top);
                acc += valid ? contrib : 0.0f;
                hf += 4.0f;
            }
        }

        // fold 4 h-phases
        acc += __shfl_xor_sync(0xffffffffu, acc, 8);
        acc += __shfl_xor_sync(0xffffffffu, acc, 16);
        if (p == 0) {
            part[n * IMG + t0 + i] = acc;
        }
    }
}

__global__ void reduce_kernel(float* __restrict__ out) {
    int idx = blockIdx.x * blockDim.x + threadIdx.x;
    const int total = NB * NANG * IMG;
    if (idx >= total) return;
    float v = 0.0f;
#pragma unroll
    for (int k = 0; k < NBANDS; ++k) {
        v += d_part[k * total + idx];
    }
    out[idx] = v;
}

extern "C" void kernel_launch(void* const* d_in, const int* in_sizes, int n_in,
                              void* d_out, int out_size) {
    const float* x      = (const float*)d_in[0];   // [2,1,512,512]
    const float* angles = (const float*)d_in[1];   // [180]
    float* out          = (float*)d_out;           // [2,180,512]

    static bool attr_set = false;
    if (!attr_set) {
        cudaFuncSetAttribute(radon_band_kernel,
                             cudaFuncAttributeMaxDynamicSharedMemorySize, SMEM_BYTES);
        attr_set = true;
    }

    {
        dim3 grid(NGROUPS, NBANDS, NB);   // 14 x 5 x 2 = 140 blocks
        radon_band_kernel<<<grid, 1024, SMEM_BYTES>>>(x, angles);
    }
    {
        const int total = NB * NANG * IMG;
        reduce_kernel<<<(total + 255) / 256, 256>>>(out);
    }
}

// round 6
// speedup vs baseline: 1.1835x; 1.1835x over previous
#include <cuda_runtime.h>
#include <cstdint>

// Radon transform: out[b, n, t] = sum_h bilinear(img_b, R(theta_n) * grid(t, h))
// B=2, N=180, H=W=512.
//
// Quad image: Q[y][x] = float4(P(y,x), P(y,x+1), P(y+1,x), P(y+1,x+1)) over the
// zero-padded grid -> each bilinear sample is ONE aligned LDG.128. Warp tile is
// 8(t) x 4(h) so each warp-load's 32 samples cover a ~10x10 px patch.
// NEW: per-(angle, t-tile) conservative h-interval skips samples that are exact
// zeros (outside (-1,512) in x or y), cutting ~13% of warp-iterations.

#define IMG 512
#define NANG 180
#define NBATCH 2
#define QPITCH 516                    // quad row pitch; valid quad cols 0..514
#define QELEMS (QPITCH * QPITCH)

__device__ float4 d_quad[NBATCH * QELEMS];

// Prologue: build quad image. P(r,c) = img[r-1][c-1] if 1<=r,c<=IMG else 0.
__global__ void quad_kernel(const float* __restrict__ x) {
    int idx = blockIdx.x * blockDim.x + threadIdx.x;
    int total = NBATCH * QELEMS;
    if (idx >= total) return;
    int b   = idx / QELEMS;
    int rem = idx - b * QELEMS;
    int r   = rem / QPITCH;
    int cc  = rem - r * QPITCH;

    const float* img = x + b * (IMG * IMG);
    float4 q = make_float4(0.0f, 0.0f, 0.0f, 0.0f);

    int r0 = r - 1, r1 = r;
    int c0 = cc - 1, c1 = cc;
    bool vr0 = (unsigned)r0 < IMG, vr1 = (unsigned)r1 < IMG;
    bool vc0 = (unsigned)c0 < IMG, vc1 = (unsigned)c1 < IMG;
    if (vr0 && vc0) q.x = img[r0 * IMG + c0];
    if (vr0 && vc1) q.y = img[r0 * IMG + c1];
    if (vr1 && vc0) q.z = img[r1 * IMG + c0];
    if (vr1 && vc1) q.w = img[r1 * IMG + c1];

    d_quad[idx] = q;
}

__global__ void __launch_bounds__(128) radon_kernel(const float* __restrict__ angles,
                                                    float* __restrict__ out) {
    const int warp = threadIdx.x >> 5;
    const int lane = threadIdx.x & 31;
    const int i = lane & 7;          // t within warp's 8-wide tile
    const int p = lane >> 3;         // h phase 0..3

    const int t0 = blockIdx.x * 32 + warp * 8;     // warp's first detector column
    const int t = t0 + i;
    const int n = blockIdx.y;                      // angle
    const int b = blockIdx.z;                      // batch

    const float ang = angles[n] * 0.017453292519943295f;   // deg2rad
    const float s = sinf(ang);
    const float c = cosf(ang);
    const float ns = -s;

    // Pixel coords (unit steps: 255.5 * 2/511 == 1.0):
    //   ix(t,h) = I0 + t*c - h*s ;  iy(t,h) = J0 + t*s + h*c
    const float I0 = 255.5f * (s - c + 1.0f);
    const float J0 = 255.5f * (1.0f - s - c);

    const float tix0 = fmaf((float)t, c, I0);
    const float tiy0 = fmaf((float)t, s, J0);

    // ---- warp-uniform conservative h-interval: nonzero samples need
    //      ix in (-1,512) and iy in (-1,512) for SOME lane i in [0,7] ----
    const float txA = fmaf((float)t0, c, I0), txB = fmaf((float)(t0 + 7), c, I0);
    const float tyA = fmaf((float)t0, s, J0), tyB = fmaf((float)(t0 + 7), s, J0);
    const float txmin = fminf(txA, txB), txmax = fmaxf(txA, txB);
    const float tymin = fminf(tyA, tyB), tymax = fmaxf(tyA, tyB);

    float hy0, hy1, hx0, hx1;
    if (fabsf(c) > 1e-5f) {
        const float inv = 1.0f / c;         // iy = ty + h*c in (-1,512)
        const float hA = (-1.0f - tymax) * inv;
        const float hB = (512.0f - tymin) * inv;
        hy0 = fminf(hA, hB); hy1 = fmaxf(hA, hB);
    } else { hy0 = 0.0f; hy1 = 511.0f; }
    if (fabsf(s) > 1e-5f) {
        const float inv = 1.0f / s;         // ix = tx - h*s in (-1,512)
        const float hA = (txmin - 512.0f) * inv;
        const float hB = (txmax + 1.0f) * inv;
        hx0 = fminf(hA, hB); hx1 = fmaxf(hA, hB);
    } else { hx0 = 0.0f; hx1 = 511.0f; }

    const float hs_f = fmaxf(fmaxf(hy0, hx0) - 1.0f, 0.0f);
    const float he_f = fminf(fminf(hy1, hx1) + 1.0f, 511.0f);
    const int hs = __float2int_rd(hs_f);
    const int he = __float2int_ru(he_f) + 1;   // exclusive end, <= 512

    const float4* __restrict__ quad = d_quad + b * QELEMS;

    float acc = 0.0f;
    if (he > hs) {
        const int kmax = (he - hs - p + 3) >> 2;   // h = hs + p + 4k < he
        float hf = (float)(hs + p);
#pragma unroll 4
        for (int k = 0; k < kmax; ++k) {
            float ix = fmaf(hf, ns, tix0);
            float iy = fmaf(hf, c,  tiy0);
            // clamp so the zero halo absorbs OOB; weights give exact zeros there.
            ix = fminf(fmaxf(ix, -1.0f), 512.0f);
            iy = fminf(fmaxf(iy, -1.0f), 512.0f);

            const int xi = __float2int_rd(ix);
            const int yi = __float2int_rd(iy);
            const float fx = ix - __int2float_rn(xi);
            const float fy = iy - __int2float_rn(yi);

            const float4 v = __ldg(quad + (yi + 1) * QPITCH + (xi + 1));

            const float top = fmaf(fx, v.y - v.x, v.x);
            const float bot = fmaf(fx, v.w - v.z, v.z);
            acc = fmaf(fy, bot - top, acc + top);
            hf += 4.0f;
        }
    }

    // Fold the 4 h-phases (lanes p=0..3 share the same t).
    acc += __shfl_xor_sync(0xffffffffu, acc, 8);
    acc += __shfl_xor_sync(0xffffffffu, acc, 16);

    if (p == 0) {
        out[(b * NANG + n) * IMG + t] = acc;
    }
}

extern "C" void kernel_launch(void* const* d_in, const int* in_sizes, int n_in,
                              void* d_out, int out_size) {
    const float* x      = (const float*)d_in[0];   // [2,1,512,512]
    const float* angles = (const float*)d_in[1];   // [180]
    float* out          = (float*)d_out;           // [2,180,512]

    {
        int total = NBATCH * QELEMS;
        int threads = 256;
        int blocks = (total + threads - 1) / threads;
        quad_kernel<<<blocks, threads>>>(x);
    }
    {
        dim3 block(128, 1, 1);
        dim3 grid(IMG / 32, NANG, NBATCH);   // 16 x 180 x 2 = 5760 blocks
        radon_kernel<<<grid, block>>>(angles, out);
    }
}

// round 8
// speedup vs baseline: 1.5541x; 1.3131x over previous
#include <cuda_runtime.h>
#include <cuda_fp16.h>
#include <cstdint>

// Radon transform: out[b, n, t] = sum_h bilinear(img_b, R(theta_n) * grid(t, h))
// B=2, N=180, H=W=512.
//
// fp16 quad image: Q[y][x] = half4(P(y,x), P(y,x+1), P(y+1,x), P(y+1,x+1)) over the
// zero-padded grid -> each bilinear sample is ONE aligned LDG.64 (8B). Halving quad
// bytes halves the warp footprint's 32B-sector count, which is the L1tex limiter.
// Warp tile 8(t) x 4(h); per-(angle,t-tile) h-interval skips exact-zero samples.
// fp16 image quantization adds ~1.4e-4 L2 rel err (threshold 1e-3).

#define IMG 512
#define NANG 180
#define NBATCH 2
#define QPITCH 516                    // quad row pitch; valid quad cols 0..514
#define QELEMS (QPITCH * QPITCH)

__device__ uint2 d_quadh[NBATCH * QELEMS];   // half4 per quad

// Prologue: build fp16 quad image. P(r,c) = img[r-1][c-1] if 1<=r,c<=IMG else 0.
__global__ void quad_kernel(const float* __restrict__ x) {
    int idx = blockIdx.x * blockDim.x + threadIdx.x;
    int total = NBATCH * QELEMS;
    if (idx >= total) return;
    int b   = idx / QELEMS;
    int rem = idx - b * QELEMS;
    int r   = rem / QPITCH;
    int cc  = rem - r * QPITCH;

    const float* img = x + b * (IMG * IMG);
    float qx = 0.0f, qy = 0.0f, qz = 0.0f, qw = 0.0f;

    int r0 = r - 1, r1 = r;
    int c0 = cc - 1, c1 = cc;
    bool vr0 = (unsigned)r0 < IMG, vr1 = (unsigned)r1 < IMG;
    bool vc0 = (unsigned)c0 < IMG, vc1 = (unsigned)c1 < IMG;
    if (vr0 && vc0) qx = img[r0 * IMG + c0];
    if (vr0 && vc1) qy = img[r0 * IMG + c1];
    if (vr1 && vc0) qz = img[r1 * IMG + c0];
    if (vr1 && vc1) qw = img[r1 * IMG + c1];

    __half2 lo = __floats2half2_rn(qx, qy);
    __half2 hi = __floats2half2_rn(qz, qw);
    uint2 q;
    q.x = *(const unsigned int*)&lo;
    q.y = *(const unsigned int*)&hi;
    d_quadh[idx] = q;
}

__global__ void __launch_bounds__(128) radon_kernel(const float* __restrict__ angles,
                                                    float* __restrict__ out) {
    const int warp = threadIdx.x >> 5;
    const int lane = threadIdx.x & 31;
    const int i = lane & 7;          // t within warp's 8-wide tile
    const int p = lane >> 3;         // h phase 0..3

    const int t0 = blockIdx.x * 32 + warp * 8;     // warp's first detector column
    const int t = t0 + i;
    const int n = blockIdx.y;                      // angle
    const int b = blockIdx.z;                      // batch

    const float ang = angles[n] * 0.017453292519943295f;   // deg2rad
    const float s = sinf(ang);
    const float c = cosf(ang);
    const float ns = -s;

    // Pixel coords (unit steps: 255.5 * 2/511 == 1.0):
    //   ix(t,h) = I0 + t*c - h*s ;  iy(t,h) = J0 + t*s + h*c
    const float I0 = 255.5f * (s - c + 1.0f);
    const float J0 = 255.5f * (1.0f - s - c);

    const float tix0 = fmaf((float)t, c, I0);
    const float tiy0 = fmaf((float)t, s, J0);

    // warp-uniform conservative h-interval: nonzero samples need
    // ix in (-1,512) and iy in (-1,512) for SOME lane i in [0,7]
    const float txA = fmaf((float)t0, c, I0), txB = fmaf((float)(t0 + 7), c, I0);
    const float tyA = fmaf((float)t0, s, J0), tyB = fmaf((float)(t0 + 7), s, J0);
    const float txmin = fminf(txA, txB), txmax = fmaxf(txA, txB);
    const float tymin = fminf(tyA, tyB), tymax = fmaxf(tyA, tyB);

    float hy0, hy1, hx0, hx1;
    if (fabsf(c) > 1e-5f) {
        const float inv = 1.0f / c;         // iy = ty + h*c in (-1,512)
        const float hA = (-1.0f - tymax) * inv;
        const float hB = (512.0f - tymin) * inv;
        hy0 = fminf(hA, hB); hy1 = fmaxf(hA, hB);
    } else { hy0 = 0.0f; hy1 = 511.0f; }
    if (fabsf(s) > 1e-5f) {
        const float inv = 1.0f / s;         // ix = tx - h*s in (-1,512)
        const float hA = (txmin - 512.0f) * inv;
        const float hB = (txmax + 1.0f) * inv;
        hx0 = fminf(hA, hB); hx1 = fmaxf(hA, hB);
    } else { hx0 = 0.0f; hx1 = 511.0f; }

    const float hs_f = fmaxf(fmaxf(hy0, hx0) - 1.0f, 0.0f);
    const float he_f = fminf(fminf(hy1, hx1) + 1.0f, 511.0f);
    const int hs = __float2int_rd(hs_f);
    const int he = __float2int_ru(he_f) + 1;   // exclusive end, <= 512

    const uint2* __restrict__ quad = d_quadh + b * QELEMS;

    float acc = 0.0f;
    if (he > hs) {
        const int kmax = (he - hs - p + 3) >> 2;   // h = hs + p + 4k < he
        float hf = (float)(hs + p);
#pragma unroll 4
        for (int k = 0; k < kmax; ++k) {
            float ix = fmaf(hf, ns, tix0);
            float iy = fmaf(hf, c,  tiy0);
            // clamp so the zero halo absorbs OOB; weights give exact zeros there.
            ix = fminf(fmaxf(ix, -1.0f), 512.0f);
            iy = fminf(fmaxf(iy, -1.0f), 512.0f);

            const int xi = __float2int_rd(ix);
            const int yi = __float2int_rd(iy);
            const float fx = ix - __int2float_rn(xi);
            const float fy = iy - __int2float_rn(yi);

            const uint2 q = __ldg(quad + (yi + 1) * QPITCH + (xi + 1));
            const float2 vt = __half22float2(*(const __half2*)&q.x);  // v00, v10
            const float2 vb = __half22float2(*(const __half2*)&q.y);  // v01, v11

            const float top = fmaf(fx, vt.y - vt.x, vt.x);
            const float bot = fmaf(fx, vb.y - vb.x, vb.x);
            acc = fmaf(fy, bot - top, acc + top);
            hf += 4.0f;
        }
    }

    // Fold the 4 h-phases (lanes p=0..3 share the same t).
    acc += __shfl_xor_sync(0xffffffffu, acc, 8);
    acc += __shfl_xor_sync(0xffffffffu, acc, 16);

    if (p == 0) {
        out[(b * NANG + n) * IMG + t] = acc;
    }
}

extern "C" void kernel_launch(void* const* d_in, const int* in_sizes, int n_in,
                              void* d_out, int out_size) {
    const float* x      = (const float*)d_in[0];   // [2,1,512,512]
    const float* angles = (const float*)d_in[1];   // [180]
    float* out          = (float*)d_out;           // [2,180,512]

    {
        int total = NBATCH * QELEMS;
        int threads = 256;
        int blocks = (total + threads - 1) / threads;
        quad_kernel<<<blocks, threads>>>(x);
    }
    {
        dim3 block(128, 1, 1);
        dim3 grid(IMG / 32, NANG, NBATCH);   // 16 x 180 x 2 = 5760 blocks
        radon_kernel<<<grid, block>>>(angles, out);
    }
}

// round 9
// speedup vs baseline: 1.6253x; 1.0458x over previous
#include <cuda_runtime.h>
#include <cuda_fp16.h>
#include <cstdint>

// Radon transform: out[b, n, t] = sum_h bilinear(img_b, R(theta_n) * grid(t, h))
// B=2, N=180, H=W=512.
//
// fp16 quad image (half4 per texel -> one LDG.64 per bilinear sample), 8(t)x4(h)
// warp tile, per-(angle,t-tile) h-interval skipping exact-zero samples, and NEW:
// the h-range is split into [edge | interior | edge] where the interior provably
// needs no coordinate clamps (they are identity there) -> 4 fewer FMNMX per
// sample on ~95% of iterations. Edge iterations keep the exact clamped body.

#define IMG 512
#define NANG 180
#define NBATCH 2
#define QPITCH 516                    // quad row pitch; valid quad cols 0..515
#define QELEMS (QPITCH * QPITCH)

__device__ uint2 d_quadh[NBATCH * QELEMS];   // half4 per quad

// Prologue: build fp16 quad image. P(r,c) = img[r-1][c-1] if 1<=r,c<=IMG else 0.
__global__ void quad_kernel(const float* __restrict__ x) {
    int idx = blockIdx.x * blockDim.x + threadIdx.x;
    int total = NBATCH * QELEMS;
    if (idx >= total) return;
    int b   = idx / QELEMS;
    int rem = idx - b * QELEMS;
    int r   = rem / QPITCH;
    int cc  = rem - r * QPITCH;

    const float* img = x + b * (IMG * IMG);
    float qx = 0.0f, qy = 0.0f, qz = 0.0f, qw = 0.0f;

    int r0 = r - 1, r1 = r;
    int c0 = cc - 1, c1 = cc;
    bool vr0 = (unsigned)r0 < IMG, vr1 = (unsigned)r1 < IMG;
    bool vc0 = (unsigned)c0 < IMG, vc1 = (unsigned)c1 < IMG;
    if (vr0 && vc0) qx = img[r0 * IMG + c0];
    if (vr0 && vc1) qy = img[r0 * IMG + c1];
    if (vr1 && vc0) qz = img[r1 * IMG + c0];
    if (vr1 && vc1) qw = img[r1 * IMG + c1];

    __half2 lo = __floats2half2_rn(qx, qy);
    __half2 hi = __floats2half2_rn(qz, qw);
    uint2 q;
    q.x = *(const unsigned int*)&lo;
    q.y = *(const unsigned int*)&hi;
    d_quadh[idx] = q;
}

__device__ __forceinline__ void sample_accum(const uint2* __restrict__ quad,
                                             float ix, float iy, float& acc) {
    const int xi = __float2int_rd(ix);
    const int yi = __float2int_rd(iy);
    const float fx = ix - __int2float_rn(xi);
    const float fy = iy - __int2float_rn(yi);

    const uint2 q = __ldg(quad + yi * QPITCH + xi);   // quad pre-offset by QPITCH+1
    const float2 vt = __half22float2(*(const __half2*)&q.x);  // v00, v10
    const float2 vb = __half22float2(*(const __half2*)&q.y);  // v01, v11

    const float top = fmaf(fx, vt.y - vt.x, vt.x);
    const float bot = fmaf(fx, vb.y - vb.x, vb.x);
    acc = fmaf(fy, bot - top, acc + top);
}

__global__ void __launch_bounds__(128) radon_kernel(const float* __restrict__ angles,
                                                    float* __restrict__ out) {
    const int warp = threadIdx.x >> 5;
    const int lane = threadIdx.x & 31;
    const int i = lane & 7;          // t within warp's 8-wide tile
    const int p = lane >> 3;         // h phase 0..3

    const int t0 = blockIdx.x * 32 + warp * 8;     // warp's first detector column
    const int t = t0 + i;
    const int n = blockIdx.y;                      // angle
    const int b = blockIdx.z;                      // batch

    const float ang = angles[n] * 0.017453292519943295f;   // deg2rad
    const float s = sinf(ang);                     // s >= 0 for 0..179 deg
    const float c = cosf(ang);
    const float ns = -s;

    // Pixel coords (unit steps): ix(t,h) = I0 + t*c - h*s ; iy(t,h) = J0 + t*s + h*c
    const float I0 = 255.5f * (s - c + 1.0f);
    const float J0 = 255.5f * (1.0f - s - c);

    const float tix0 = fmaf((float)t, c, I0);
    const float tiy0 = fmaf((float)t, s, J0);

    const float txA = fmaf((float)t0, c, I0), txB = fmaf((float)(t0 + 7), c, I0);
    const float tyA = fmaf((float)t0, s, J0), tyB = fmaf((float)(t0 + 7), s, J0);
    const float txmin = fminf(txA, txB), txmax = fmaxf(txA, txB);
    const float tymin = fminf(tyA, tyB), tymax = fmaxf(tyA, tyB);

    // ---- outer interval: SOME lane nonzero (ix,iy in (-1,512)), padded +-1 ----
    float hy0, hy1, hx0, hx1;
    if (fabsf(c) > 1e-5f) {
        const float inv = 1.0f / c;
        const float hA = (-1.0f - tymax) * inv;
        const float hB = (512.0f - tymin) * inv;
        hy0 = fminf(hA, hB); hy1 = fmaxf(hA, hB);
    } else { hy0 = 0.0f; hy1 = 511.0f; }
    if (s > 1e-5f) {
        const float inv = 1.0f / s;
        const float hA = (txmin - 512.0f) * inv;
        const float hB = (txmax + 1.0f) * inv;
        hx0 = fminf(hA, hB); hx1 = fmaxf(hA, hB);
    } else { hx0 = 0.0f; hx1 = 511.0f; }

    const int hs = __float2int_rd(fmaxf(fmaxf(hy0, hx0) - 1.0f, 0.0f));
    const int he = __float2int_ru(fminf(fminf(hy1, hx1) + 1.0f, 511.0f)) + 1;

    // ---- interior interval: ALL lanes have ix,iy in [-1,512] (clamps identity).
    //      Angle set has min nonzero |s|,|c| = sin(1deg)=0.0175 -> div error
    //      <= ~3.4e-3 h-units << 0.0625 inset. ----
    float xlo, xhi, ylo, yhi;
    if (s > 1e-2f) {
        const float inv = 1.0f / s;
        xlo = (txmax - 512.0f) * inv;    // h >= this  -> all ix <= 512
        xhi = (txmin + 1.0f) * inv;      // h <= this  -> all ix >= -1
    } else { xlo = -1e30f; xhi = 1e30f; }
    if (fabsf(c) > 1e-2f) {
        const float inv = 1.0f / c;
        const float hA = (-1.0f - tymin) * inv;
        const float hB = (512.0f - tymax) * inv;
        ylo = fminf(hA, hB); yhi = fmaxf(hA, hB);
    } else { ylo = -1e30f; yhi = 1e30f; }

    const float ilo = fmaxf(xlo, ylo) + 0.0625f;
    const float ihi = fminf(xhi, yhi) - 0.0625f;
    int his = __float2int_ru(fminf(fmaxf(ilo, 0.0f), 520.0f));
    int hie = __float2int_rd(fminf(fmaxf(ihi, -1.0f), 511.0f)) + 1;
    his = min(max(his, hs), he);
    hie = min(max(hie, his), he);

    const uint2* __restrict__ quad = d_quadh + b * QELEMS + (QPITCH + 1);

    float acc = 0.0f;

    // edge 1: [hs, his) with clamps
    {
        const int kmax = (his - hs - p + 3) >> 2;
        float hf = (float)(hs + p);
        for (int k = 0; k < kmax; ++k) {
            float ix = fmaf(hf, ns, tix0);
            float iy = fmaf(hf, c,  tiy0);
            ix = fminf(fmaxf(ix, -1.0f), 512.0f);
            iy = fminf(fmaxf(iy, -1.0f), 512.0f);
            sample_accum(quad, ix, iy, acc);
            hf += 4.0f;
        }
    }
    // interior: [his, hie) no clamps (identity there, bitwise identical results)
    {
        const int kmax = (hie - his - p + 3) >> 2;
        float hf = (float)(his + p);
#pragma unroll 4
        for (int k = 0; k < kmax; ++k) {
            const float ix = fmaf(hf, ns, tix0);
            const float iy = fmaf(hf, c,  tiy0);
            sample_accum(quad, ix, iy, acc);
            hf += 4.0f;
        }
    }
    // edge 2: [hie, he) with clamps
    {
        const int kmax = (he - hie - p + 3) >> 2;
        float hf = (float)(hie + p);
        for (int k = 0; k < kmax; ++k) {
            float ix = fmaf(hf, ns, tix0);
            float iy = fmaf(hf, c,  tiy0);
            ix = fminf(fmaxf(ix, -1.0f), 512.0f);
            iy = fminf(fmaxf(iy, -1.0f), 512.0f);
            sample_accum(quad, ix, iy, acc);
            hf += 4.0f;
        }
    }

    // Fold the 4 h-phases (lanes p=0..3 share the same t).
    acc += __shfl_xor_sync(0xffffffffu, acc, 8);
    acc += __shfl_xor_sync(0xffffffffu, acc, 16);

    if (p == 0) {
        out[(b * NANG + n) * IMG + t] = acc;
    }
}

extern "C" void kernel_launch(void* const* d_in, const int* in_sizes, int n_in,
                              void* d_out, int out_size) {
    const float* x      = (const float*)d_in[0];   // [2,1,512,512]
    const float* angles = (const float*)d_in[1];   // [180]
    float* out          = (float*)d_out;           // [2,180,512]

    {
        int total = NBATCH * QELEMS;
        int threads = 256;
        int blocks = (total + threads - 1) / threads;
        quad_kernel<<<blocks, threads>>>(x);
    }
    {
        dim3 block(128, 1, 1);
        dim3 grid(IMG / 32, NANG, NBATCH);   // 16 x 180 x 2 = 5760 blocks
        radon_kernel<<<grid, block>>>(angles, out);
    }
}

// round 10
// speedup vs baseline: 1.7819x; 1.0963x over previous
#include <cuda_runtime.h>
#include <cuda_fp16.h>
#include <cstdint>

// Radon transform: out[b, n, t] = sum_h bilinear(img_b, R(theta_n) * grid(t, h))
// B=2, N=180, H=W=512.
//
// fp16 quad image stored as COLUMN PAIRS: q.x=(v00,v01), q.y=(v10,v11), so the
// x-lerp is one HFMA2 on packed halves BEFORE unpacking (saves 3 instr/sample).
// One LDG.64 per bilinear sample; 8(t)x4(h) warp tile; per-(angle,t-tile)
// h-interval skips exact-zero samples; clamp-free interior loop.

#define IMG 512
#define NANG 180
#define NBATCH 2
#define QPITCH 516                    // quad row pitch; valid quad cols 0..515
#define QELEMS (QPITCH * QPITCH)

__device__ uint2 d_quadh[NBATCH * QELEMS];   // (v00,v01) | (v10,v11) as half2 pair

// Prologue: build fp16 column-pair quad image. P(r,c)=img[r-1][c-1] in-bounds else 0.
__global__ void quad_kernel(const float* __restrict__ x) {
    int idx = blockIdx.x * blockDim.x + threadIdx.x;
    int total = NBATCH * QELEMS;
    if (idx >= total) return;
    int b   = idx / QELEMS;
    int rem = idx - b * QELEMS;
    int r   = rem / QPITCH;
    int cc  = rem - r * QPITCH;

    const float* img = x + b * (IMG * IMG);
    float v00 = 0.0f, v10 = 0.0f, v01 = 0.0f, v11 = 0.0f;

    int r0 = r - 1, r1 = r;
    int c0 = cc - 1, c1 = cc;
    bool vr0 = (unsigned)r0 < IMG, vr1 = (unsigned)r1 < IMG;
    bool vc0 = (unsigned)c0 < IMG, vc1 = (unsigned)c1 < IMG;
    if (vr0 && vc0) v00 = img[r0 * IMG + c0];
    if (vr0 && vc1) v10 = img[r0 * IMG + c1];
    if (vr1 && vc0) v01 = img[r1 * IMG + c0];
    if (vr1 && vc1) v11 = img[r1 * IMG + c1];

    __half2 left  = __floats2half2_rn(v00, v01);   // left column  (y0, y1)
    __half2 right = __floats2half2_rn(v10, v11);   // right column (y0, y1)
    uint2 q;
    q.x = *(const unsigned int*)&left;
    q.y = *(const unsigned int*)&right;
    d_quadh[idx] = q;
}

__device__ __forceinline__ void sample_accum(const uint2* __restrict__ quad,
                                             float ix, float iy, float& acc) {
    const int xi = __float2int_rd(ix);
    const int yi = __float2int_rd(iy);
    const float fx = ix - __int2float_rn(xi);
    const float fy = iy - __int2float_rn(yi);

    const uint2 q = __ldg(quad + yi * QPITCH + xi);   // quad pre-offset by QPITCH+1
    const __half2 left  = *(const __half2*)&q.x;      // (v00, v01)
    const __half2 right = *(const __half2*)&q.y;      // (v10, v11)

    const __half2 fx2 = __float2half2_rn(fx);
    const __half2 tb  = __hfma2(fx2, __hsub2(right, left), left);  // (top, bot)
    const float2  f2  = __half22float2(tb);

    const float contrib = fmaf(fy, f2.y - f2.x, f2.x);
    acc += contrib;                                    // short 4-cyc chain
}

__global__ void __launch_bounds__(128) radon_kernel(const float* __restrict__ angles,
                                                    float* __restrict__ out) {
    const int warp = threadIdx.x >> 5;
    const int lane = threadIdx.x & 31;
    const int i = lane & 7;          // t within warp's 8-wide tile
    const int p = lane >> 3;         // h phase 0..3

    const int t0 = blockIdx.x * 32 + warp * 8;     // warp's first detector column
    const int t = t0 + i;
    const int n = blockIdx.y;                      // angle
    const int b = blockIdx.z;                      // batch

    const float ang = angles[n] * 0.017453292519943295f;   // deg2rad
    const float s = sinf(ang);                     // s >= 0 for 0..179 deg
    const float c = cosf(ang);
    const float ns = -s;

    // Pixel coords (unit steps): ix(t,h) = I0 + t*c - h*s ; iy(t,h) = J0 + t*s + h*c
    const float I0 = 255.5f * (s - c + 1.0f);
    const float J0 = 255.5f * (1.0f - s - c);

    const float tix0 = fmaf((float)t, c, I0);
    const float tiy0 = fmaf((float)t, s, J0);

    const float txA = fmaf((float)t0, c, I0), txB = fmaf((float)(t0 + 7), c, I0);
    const float tyA = fmaf((float)t0, s, J0), tyB = fmaf((float)(t0 + 7), s, J0);
    const float txmin = fminf(txA, txB), txmax = fmaxf(txA, txB);
    const float tymin = fminf(tyA, tyB), tymax = fmaxf(tyA, tyB);

    // ---- outer interval: SOME lane nonzero (ix,iy in (-1,512)), padded +-1 ----
    float hy0, hy1, hx0, hx1;
    if (fabsf(c) > 1e-5f) {
        const float inv = 1.0f / c;
        const float hA = (-1.0f - tymax) * inv;
        const float hB = (512.0f - tymin) * inv;
        hy0 = fminf(hA, hB); hy1 = fmaxf(hA, hB);
    } else { hy0 = 0.0f; hy1 = 511.0f; }
    if (s > 1e-5f) {
        const float inv = 1.0f / s;
        const float hA = (txmin - 512.0f) * inv;
        const float hB = (txmax + 1.0f) * inv;
        hx0 = fminf(hA, hB); hx1 = fmaxf(hA, hB);
    } else { hx0 = 0.0f; hx1 = 511.0f; }

    const int hs = __float2int_rd(fmaxf(fmaxf(hy0, hx0) - 1.0f, 0.0f));
    const int he = __float2int_ru(fminf(fminf(hy1, hx1) + 1.0f, 511.0f)) + 1;

    // ---- interior interval: ALL lanes have ix,iy in [-1,512] (clamps identity).
    //      Min nonzero |s|,|c| = sin(1deg)=0.0175 -> div error << 0.0625 inset. ----
    float xlo, xhi, ylo, yhi;
    if (s > 1e-2f) {
        const float inv = 1.0f / s;
        xlo = (txmax - 512.0f) * inv;    // h >= this -> all ix <= 512
        xhi = (txmin + 1.0f) * inv;      // h <= this -> all ix >= -1
    } else { xlo = -1e30f; xhi = 1e30f; }
    if (fabsf(c) > 1e-2f) {
        const float inv = 1.0f / c;
        const float hA = (-1.0f - tymin) * inv;
        const float hB = (512.0f - tymax) * inv;
        ylo = fminf(hA, hB); yhi = fmaxf(hA, hB);
    } else { ylo = -1e30f; yhi = 1e30f; }

    const float ilo = fmaxf(xlo, ylo) + 0.0625f;
    const float ihi = fminf(xhi, yhi) - 0.0625f;
    int his = __float2int_ru(fminf(fmaxf(ilo, 0.0f), 520.0f));
    int hie = __float2int_rd(fminf(fmaxf(ihi, -1.0f), 511.0f)) + 1;
    his = min(max(his, hs), he);
    hie = min(max(hie, his), he);

    const uint2* __restrict__ quad = d_quadh + b * QELEMS + (QPITCH + 1);

    float acc = 0.0f;

    // edge 1: [hs, his) with clamps
    {
        const int kmax = (his - hs - p + 3) >> 2;
        float hf = (float)(hs + p);
        for (int k = 0; k < kmax; ++k) {
            float ix = fmaf(hf, ns, tix0);
            float iy = fmaf(hf, c,  tiy0);
            ix = fminf(fmaxf(ix, -1.0f), 512.0f);
            iy = fminf(fmaxf(iy, -1.0f), 512.0f);
            sample_accum(quad, ix, iy, acc);
            hf += 4.0f;
        }
    }
    // interior: [his, hie) no clamps (identity there)
    {
        const int kmax = (hie - his - p + 3) >> 2;
        float hf = (float)(his + p);
#pragma unroll 4
        for (int k = 0; k < kmax; ++k) {
            const float ix = fmaf(hf, ns, tix0);
            const float iy = fmaf(hf, c,  tiy0);
            sample_accum(quad, ix, iy, acc);
            hf += 4.0f;
        }
    }
    // edge 2: [hie, he) with clamps
    {
        const int kmax = (he - hie - p + 3) >> 2;
        float hf = (float)(hie + p);
        for (int k = 0; k < kmax; ++k) {
            float ix = fmaf(hf, ns, tix0);
            float iy = fmaf(hf, c,  tiy0);
            ix = fminf(fmaxf(ix, -1.0f), 512.0f);
            iy = fminf(fmaxf(iy, -1.0f), 512.0f);
            sample_accum(quad, ix, iy, acc);
            hf += 4.0f;
        }
    }

    // Fold the 4 h-phases (lanes p=0..3 share the same t).
    acc += __shfl_xor_sync(0xffffffffu, acc, 8);
    acc += __shfl_xor_sync(0xffffffffu, acc, 16);

    if (p == 0) {
        out[(b * NANG + n) * IMG + t] = acc;
    }
}

extern "C" void kernel_launch(void* const* d_in, const int* in_sizes, int n_in,
                              void* d_out, int out_size) {
    const float* x      = (const float*)d_in[0];   // [2,1,512,512]
    const float* angles = (const float*)d_in[1];   // [180]
    float* out          = (float*)d_out;           // [2,180,512]

    {
        int total = NBATCH * QELEMS;
        int threads = 256;
        int blocks = (total + threads - 1) / threads;
        quad_kernel<<<blocks, threads>>>(x);
    }
    {
        dim3 block(128, 1, 1);
        dim3 grid(IMG / 32, NANG, NBATCH);   // 16 x 180 x 2 = 5760 blocks
        radon_kernel<<<grid, block>>>(angles, out);
    }
}

// round 11
// speedup vs baseline: 1.8077x; 1.0145x over previous
#include <cuda_runtime.h>
#include <cuda_fp16.h>
#include <cstdint>

// Radon transform: out[b, n, t] = sum_h bilinear(img_b, R(theta_n) * grid(t, h))
// B=2, N=180, H=W=512.
//
// fp16 delta-quad image: q.x=(v00,v01), q.y=(v10-v00, v11-v01) -> x-lerp is one
// HFMA2 on packed halves. One LDG.64 per sample; 8(t)x4(h) warp tile; h-interval
// zero-skip; clamp-free interior. NEW: magic-number floor/fract via __fadd_rd
// (exact for ix in [-1,512]) -> no F2I/I2F; quad index = float bits & 0xFFF.

#define IMG 512
#define NANG 180
#define NBATCH 2
#define QPITCH 516                    // quad row pitch; valid quad rows/cols 0..515
#define QELEMS (QPITCH * QPITCH)
#define MAGIC1 12582913.0f            // 2^23 + 2^22 + 1

__device__ uint2 d_quadh[NBATCH * QELEMS];   // (v00,v01) | (dx_top,dx_bot) half2 pair

// Prologue: build fp16 delta-quad image. P(r,c)=img[r-1][c-1] in-bounds else 0.
__global__ void quad_kernel(const float* __restrict__ x) {
    int idx = blockIdx.x * blockDim.x + threadIdx.x;
    int total = NBATCH * QELEMS;
    if (idx >= total) return;
    int b   = idx / QELEMS;
    int rem = idx - b * QELEMS;
    int r   = rem / QPITCH;
    int cc  = rem - r * QPITCH;

    const float* img = x + b * (IMG * IMG);
    float v00 = 0.0f, v10 = 0.0f, v01 = 0.0f, v11 = 0.0f;

    int r0 = r - 1, r1 = r;
    int c0 = cc - 1, c1 = cc;
    bool vr0 = (unsigned)r0 < IMG, vr1 = (unsigned)r1 < IMG;
    bool vc0 = (unsigned)c0 < IMG, vc1 = (unsigned)c1 < IMG;
    if (vr0 && vc0) v00 = img[r0 * IMG + c0];
    if (vr0 && vc1) v10 = img[r0 * IMG + c1];
    if (vr1 && vc0) v01 = img[r1 * IMG + c0];
    if (vr1 && vc1) v11 = img[r1 * IMG + c1];

    __half2 left  = __floats2half2_rn(v00, v01);              // (v00, v01)
    __half2 delta = __floats2half2_rn(v10 - v00, v11 - v01);  // (dx_top, dx_bot)
    uint2 q;
    q.x = *(const unsigned int*)&left;
    q.y = *(const unsigned int*)&delta;
    d_quadh[idx] = q;
}

// ix, iy must be in [-1, 512].
__device__ __forceinline__ void sample_accum(const uint2* __restrict__ quad,
                                             float ix, float iy, float& acc) {
    // magic floor: f = MAGIC1 + floor(v)+1 exactly; index = bits & 0xFFF in [0,513]
    const float fxm = __fadd_rd(ix, MAGIC1);
    const float fym = __fadd_rd(iy, MAGIC1);
    const float fx = ix - (fxm - MAGIC1);        // exact fract in [0,1)
    const float fy = iy - (fym - MAGIC1);
    const int xi1 = __float_as_int(fxm) & 0xFFF; // floor(ix)+1
    const int yi1 = __float_as_int(fym) & 0xFFF; // floor(iy)+1

    const uint2 q = __ldg(quad + yi1 * QPITCH + xi1);
    const __half2 left  = *(const __half2*)&q.x;  // (v00, v01)
    const __half2 delta = *(const __half2*)&q.y;  // (v10-v00, v11-v01)

    const __half2 fx2 = __floats2half2_rn(fx, fx);
    const __half2 tb  = __hfma2(fx2, delta, left);            // (top, bot)
    const float2  f2  = __half22float2(tb);

    acc += fmaf(fy, f2.y - f2.x, f2.x);
}

__global__ void __launch_bounds__(128) radon_kernel(const float* __restrict__ angles,
                                                    float* __restrict__ out) {
    const int warp = threadIdx.x >> 5;
    const int lane = threadIdx.x & 31;
    const int i = lane & 7;          // t within warp's 8-wide tile
    const int p = lane >> 3;         // h phase 0..3

    const int t0 = blockIdx.x * 32 + warp * 8;     // warp's first detector column
    const int t = t0 + i;
    const int n = blockIdx.y;                      // angle
    const int b = blockIdx.z;                      // batch

    const float ang = angles[n] * 0.017453292519943295f;   // deg2rad
    const float s = sinf(ang);                     // s >= 0 for 0..179 deg
    const float c = cosf(ang);
    const float ns = -s;

    // Pixel coords (unit steps): ix(t,h) = I0 + t*c - h*s ; iy(t,h) = J0 + t*s + h*c
    const float I0 = 255.5f * (s - c + 1.0f);
    const float J0 = 255.5f * (1.0f - s - c);

    const float tix0 = fmaf((float)t, c, I0);
    const float tiy0 = fmaf((float)t, s, J0);

    const float txA = fmaf((float)t0, c, I0), txB = fmaf((float)(t0 + 7), c, I0);
    const float tyA = fmaf((float)t0, s, J0), tyB = fmaf((float)(t0 + 7), s, J0);
    const float txmin = fminf(txA, txB), txmax = fmaxf(txA, txB);
    const float tymin = fminf(tyA, tyB), tymax = fmaxf(tyA, tyB);

    // ---- outer interval: SOME lane nonzero (ix,iy in (-1,512)), padded +-1 ----
    float hy0, hy1, hx0, hx1;
    if (fabsf(c) > 1e-5f) {
        const float inv = 1.0f / c;
        const float hA = (-1.0f - tymax) * inv;
        const float hB = (512.0f - tymin) * inv;
        hy0 = fminf(hA, hB); hy1 = fmaxf(hA, hB);
    } else { hy0 = 0.0f; hy1 = 511.0f; }
    if (s > 1e-5f) {
        const float inv = 1.0f / s;
        const float hA = (txmin - 512.0f) * inv;
        const float hB = (txmax + 1.0f) * inv;
        hx0 = fminf(hA, hB); hx1 = fmaxf(hA, hB);
    } else { hx0 = 0.0f; hx1 = 511.0f; }

    const int hs = __float2int_rd(fmaxf(fmaxf(hy0, hx0) - 1.0f, 0.0f));
    const int he = __float2int_ru(fminf(fminf(hy1, hx1) + 1.0f, 511.0f)) + 1;

    // ---- interior interval: ALL lanes have ix,iy in [-1,512] (clamps identity).
    //      Min nonzero |s|,|c| = sin(1deg)=0.0175 -> div error << 0.0625 inset. ----
    float xlo, xhi, ylo, yhi;
    if (s > 1e-2f) {
        const float inv = 1.0f / s;
        xlo = (txmax - 512.0f) * inv;    // h >= this -> all ix <= 512
        xhi = (txmin + 1.0f) * inv;      // h <= this -> all ix >= -1
    } else { xlo = -1e30f; xhi = 1e30f; }
    if (fabsf(c) > 1e-2f) {
        const float inv = 1.0f / c;
        const float hA = (-1.0f - tymin) * inv;
        const float hB = (512.0f - tymax) * inv;
        ylo = fminf(hA, hB); yhi = fmaxf(hA, hB);
    } else { ylo = -1e30f; yhi = 1e30f; }

    const float ilo = fmaxf(xlo, ylo) + 0.0625f;
    const float ihi = fminf(xhi, yhi) - 0.0625f;
    int his = __float2int_ru(fminf(fmaxf(ilo, 0.0f), 520.0f));
    int hie = __float2int_rd(fminf(fmaxf(ihi, -1.0f), 511.0f)) + 1;
    his = min(max(his, hs), he);
    hie = min(max(hie, his), he);

    const uint2* __restrict__ quad = d_quadh + b * QELEMS;

    float acc = 0.0f;

    // edge 1: [hs, his) with clamps
    {
        const int kmax = (his - hs - p + 3) >> 2;
        float hf = (float)(hs + p);
        for (int k = 0; k < kmax; ++k) {
            float ix = fmaf(hf, ns, tix0);
            float iy = fmaf(hf, c,  tiy0);
            ix = fminf(fmaxf(ix, -1.0f), 512.0f);
            iy = fminf(fmaxf(iy, -1.0f), 512.0f);
            sample_accum(quad, ix, iy, acc);
            hf += 4.0f;
        }
    }
    // interior: [his, hie) no clamps (identity there)
    {
        const int kmax = (hie - his - p + 3) >> 2;
        float hf = (float)(his + p);
#pragma unroll 4
        for (int k = 0; k < kmax; ++k) {
            const float ix = fmaf(hf, ns, tix0);
            const float iy = fmaf(hf, c,  tiy0);
            sample_accum(quad, ix, iy, acc);
            hf += 4.0f;
        }
    }
    // edge 2: [hie, he) with clamps
    {
        const int kmax = (he - hie - p + 3) >> 2;
        float hf = (float)(hie + p);
        for (int k = 0; k < kmax; ++k) {
            float ix = fmaf(hf, ns, tix0);
            float iy = fmaf(hf, c,  tiy0);
            ix = fminf(fmaxf(ix, -1.0f), 512.0f);
            iy = fminf(fmaxf(iy, -1.0f), 512.0f);
            sample_accum(quad, ix, iy, acc);
            hf += 4.0f;
        }
    }

    // Fold the 4 h-phases (lanes p=0..3 share the same t).
    acc += __shfl_xor_sync(0xffffffffu, acc, 8);
    acc += __shfl_xor_sync(0xffffffffu, acc, 16);

    if (p == 0) {
        out[(b * NANG + n) * IMG + t] = acc;
    }
}

extern "C" void kernel_launch(void* const* d_in, const int* in_sizes, int n_in,
                              void* d_out, int out_size) {
    const float* x      = (const float*)d_in[0];   // [2,1,512,512]
    const float* angles = (const float*)d_in[1];   // [180]
    float* out          = (float*)d_out;           // [2,180,512]

    {
        int total = NBATCH * QELEMS;
        int threads = 256;
        int blocks = (total + threads - 1) / threads;
        quad_kernel<<<blocks, threads>>>(x);
    }
    {
        dim3 block(128, 1, 1);
        dim3 grid(IMG / 32, NANG, NBATCH);   // 16 x 180 x 2 = 5760 blocks
        radon_kernel<<<grid, block>>>(angles, out);
    }
}